// round 3
// baseline (speedup 1.0000x reference)
#include <cuda_runtime.h>
#include <cuda_bf16.h>
#include <math.h>

#define NN 50000
#define EE 800000
#define HH 64
#define LL 14
#define INF_ 128
#define OUTF 112
#define MSG_EPS 1e-7f
#define LN_EPS 1e-5f

// ---------------- scratch (static device globals; no allocation) ----------------
__device__ float g_h[NN * HH];     // current node features
__device__ float g_h2[NN * HH];    // relu(LN(h)) per layer
__device__ float g_agg[NN * HH];   // softmax aggregation result
__device__ int   g_deg[NN];
__device__ int   g_cur[NN];
__device__ int   g_off[NN + 1];
__device__ int   g_srt_src[EE];    // src indices bucketed by dst

// ---------------- CSR build ----------------
__global__ void k_zero() {
    int i = blockIdx.x * blockDim.x + threadIdx.x;
    if (i < NN) { g_deg[i] = 0; g_cur[i] = 0; }
}

__global__ void k_hist(const int* __restrict__ dst) {
    int e = blockIdx.x * blockDim.x + threadIdx.x;
    if (e < EE) atomicAdd(&g_deg[dst[e]], 1);
}

__global__ void k_scan() {
    __shared__ int part[1024];
    const int tid = threadIdx.x;
    const int CH = (NN + 1023) / 1024;  // 49
    int beg = tid * CH;
    int end = min(beg + CH, NN);
    int s = 0;
    for (int i = beg; i < end; i++) s += g_deg[i];
    part[tid] = s;
    __syncthreads();
    for (int off = 1; off < 1024; off <<= 1) {
        int v = 0;
        if (tid >= off) v = part[tid - off];
        __syncthreads();
        if (tid >= off) part[tid] += v;
        __syncthreads();
    }
    int run = part[tid] - s;
    for (int i = beg; i < end; i++) { g_off[i] = run; run += g_deg[i]; }
    if (tid == 1023) g_off[NN] = run;
}

__global__ void k_scatter(const int* __restrict__ src,
                          const int* __restrict__ dst) {
    int e = blockIdx.x * blockDim.x + threadIdx.x;
    if (e < EE) {
        int d = dst[e];
        int pos = g_off[d] + atomicAdd(&g_cur[d], 1);
        g_srt_src[pos] = src[e];
    }
}

// ---------------- encoder: h = x @ enc_W + enc_b  (16 nodes per block) ----------------
__global__ void __launch_bounds__(256) k_enc(const float* __restrict__ x,
                                             const float* __restrict__ W,
                                             const float* __restrict__ b) {
    __shared__ float Ws[INF_ * HH];  // 32 KB
    __shared__ float xs[4][INF_];
    int tid = threadIdx.x;
    int nl = tid >> 6, j = tid & 63;
    for (int i = tid; i < INF_ * HH; i += 256) Ws[i] = W[i];
    float bj = b[j];
    #pragma unroll
    for (int it = 0; it < 4; it++) {
        int n = blockIdx.x * 16 + it * 4 + nl;
        __syncthreads();
        if (n < NN) {
            xs[nl][j]      = x[n * INF_ + j];
            xs[nl][j + 64] = x[n * INF_ + j + 64];
        }
        __syncthreads();
        if (n < NN) {
            float acc = bj;
            #pragma unroll
            for (int k = 0; k < INF_; k++) acc = fmaf(xs[nl][k], Ws[k * HH + j], acc);
            g_h[n * HH + j] = acc;
        }
    }
}

// ---------------- LayerNorm + ReLU: g_h2 = relu(LN(g_h)) ----------------
__global__ void __launch_bounds__(256) k_ln(const float* __restrict__ gma,
                                            const float* __restrict__ bta) {
    int warp = (blockIdx.x * blockDim.x + threadIdx.x) >> 5;
    int lane = threadIdx.x & 31;
    if (warp >= NN) return;
    float2 v = *(const float2*)(g_h + warp * HH + lane * 2);
    float s = v.x + v.y;
    #pragma unroll
    for (int o = 16; o; o >>= 1) s += __shfl_xor_sync(0xffffffffu, s, o);
    float mu = s * (1.f / 64.f);
    float dx = v.x - mu, dy = v.y - mu;
    float vs = dx * dx + dy * dy;
    #pragma unroll
    for (int o = 16; o; o >>= 1) vs += __shfl_xor_sync(0xffffffffu, vs, o);
    float rs = rsqrtf(vs * (1.f / 64.f) + LN_EPS);
    float2 gg = *(const float2*)(gma + lane * 2);
    float2 bb = *(const float2*)(bta + lane * 2);
    float2 o2;
    o2.x = fmaxf(fmaf(dx * rs, gg.x, bb.x), 0.f);
    o2.y = fmaxf(fmaf(dy * rs, gg.y, bb.y), 0.f);
    *(float2*)(g_h2 + warp * HH + lane * 2) = o2;
}

// ---------------- softmax aggregation, single pass, warp per node ----------------
// msg = relu(h)+eps <= ~8 after LN, so exp(msg) cannot overflow; max-shift is
// mathematically redundant: agg = sum(m*e^m)/sum(e^m).
__global__ void __launch_bounds__(256) k_agg(int use_h2) {
    const float* __restrict__ hsrc = use_h2 ? g_h2 : g_h;
    int warp = (blockIdx.x * blockDim.x + threadIdx.x) >> 5;
    int lane = threadIdx.x & 31;
    if (warp >= NN) return;
    int beg = g_off[warp], end = g_off[warp + 1];
    float d0 = 0.f, d1 = 0.f, n0 = 0.f, n1 = 0.f;
    for (int base = beg; base < end; base += 32) {
        int cnt = min(32, end - base);
        int idx = 0;
        if (lane < cnt) idx = g_srt_src[base + lane];  // one coalesced load per 32 edges
        #pragma unroll 4
        for (int t = 0; t < cnt; t++) {
            int s = __shfl_sync(0xffffffffu, idx, t);
            float2 v = *(const float2*)(hsrc + s * HH + lane * 2);
            float m0 = fmaxf(v.x, 0.f) + MSG_EPS;
            float m1 = fmaxf(v.y, 0.f) + MSG_EPS;
            float e0 = __expf(m0);
            float e1 = __expf(m1);
            d0 += e0; n0 = fmaf(m0, e0, n0);
            d1 += e1; n1 = fmaf(m1, e1, n1);
        }
    }
    float2 o;
    o.x = n0 / fmaxf(d0, 1e-16f);   // empty segment -> 0, matches reference
    o.y = n1 / fmaxf(d1, 1e-16f);
    *(float2*)(g_agg + warp * HH + lane * 2) = o;
}

// ---------------- combine + 64x64 GEMM (16 nodes per block) ----------------
__global__ void __launch_bounds__(256) k_mat(const float* __restrict__ W,
                                             const float* __restrict__ b,
                                             int use_h2, int res) {
    __shared__ float Ws[HH * HH];  // 16 KB
    __shared__ float ts[4][HH];
    int tid = threadIdx.x;
    int nl = tid >> 6, j = tid & 63;
    for (int i = tid; i < HH * HH; i += 256) Ws[i] = W[i];
    float bj = b[j];
    const float* base = use_h2 ? g_h2 : g_h;
    #pragma unroll
    for (int it = 0; it < 4; it++) {
        int n = blockIdx.x * 16 + it * 4 + nl;
        __syncthreads();
        if (n < NN) ts[nl][j] = base[n * HH + j] + g_agg[n * HH + j];
        __syncthreads();
        if (n < NN) {
            float acc = bj + (res ? g_h[n * HH + j] : 0.f);
            #pragma unroll
            for (int k = 0; k < HH; k++) acc = fmaf(ts[nl][k], Ws[k * HH + j], acc);
            g_h[n * HH + j] = acc;
        }
    }
}

// ---------------- predictor: out = h @ pred_W + pred_b (16 nodes per block) ----------------
__global__ void __launch_bounds__(224) k_pred(const float* __restrict__ W,
                                              const float* __restrict__ b,
                                              float* __restrict__ out) {
    __shared__ float Ws[HH * OUTF];  // 28 KB
    __shared__ float hs[2][HH];
    int tid = threadIdx.x;
    for (int i = tid; i < HH * OUTF; i += 224) Ws[i] = W[i];
    int nl = tid / OUTF, j = tid % OUTF;
    float bj = b[j];
    #pragma unroll
    for (int it = 0; it < 8; it++) {
        __syncthreads();
        if (tid < 128) {
            int gl = tid >> 6, k = tid & 63;
            int nn = blockIdx.x * 16 + it * 2 + gl;
            hs[gl][k] = (nn < NN) ? g_h[nn * HH + k] : 0.f;
        }
        __syncthreads();
        int n = blockIdx.x * 16 + it * 2 + nl;
        if (n < NN) {
            float acc = bj;
            #pragma unroll
            for (int k = 0; k < HH; k++) acc = fmaf(hs[nl][k], Ws[k * OUTF + j], acc);
            out[n * OUTF + j] = acc;
        }
    }
}

// ---------------- launch ----------------
extern "C" void kernel_launch(void* const* d_in, const int* in_sizes, int n_in,
                              void* d_out, int out_size) {
    const float* x      = (const float*)d_in[0];
    const int*   ei     = (const int*)d_in[1];   // int32 (jax x64 disabled)
    const float* enc_W  = (const float*)d_in[2];
    const float* enc_b  = (const float*)d_in[3];
    const float* ln_g   = (const float*)d_in[4];
    const float* ln_b   = (const float*)d_in[5];
    const float* mlp_W  = (const float*)d_in[6];
    const float* mlp_b  = (const float*)d_in[7];
    const float* pred_W = (const float*)d_in[8];
    const float* pred_b = (const float*)d_in[9];
    float*       out    = (float*)d_out;

    const int* src = ei;
    const int* dst = ei + EE;

    // CSR build (counting sort by dst)
    k_zero<<<(NN + 255) / 256, 256>>>();
    k_hist<<<(EE + 255) / 256, 256>>>(dst);
    k_scan<<<1, 1024>>>();
    k_scatter<<<(EE + 255) / 256, 256>>>(src, dst);

    // encoder
    k_enc<<<(NN + 15) / 16, 256>>>(x, enc_W, enc_b);

    const int agg_blocks = (NN * 32 + 255) / 256;  // warp per node

    // layer 0: no pre-norm, no residual
    k_agg<<<agg_blocks, 256>>>(0);
    k_mat<<<(NN + 15) / 16, 256>>>(mlp_W, mlp_b, /*use_h2=*/0, /*res=*/0);

    // layers 1..13: h2 = relu(LN(h)); h = genconv(h2) + h
    for (int i = 1; i < LL; i++) {
        k_ln<<<(NN * 32 + 255) / 256, 256>>>(ln_g + (i - 1) * HH, ln_b + (i - 1) * HH);
        k_agg<<<agg_blocks, 256>>>(1);
        k_mat<<<(NN + 15) / 16, 256>>>(mlp_W + i * HH * HH, mlp_b + i * HH, 1, 1);
    }

    // predictor
    k_pred<<<(NN + 15) / 16, 224>>>(pred_W, pred_b, out);
}

// round 4
// speedup vs baseline: 1.3889x; 1.3889x over previous
#include <cuda_runtime.h>
#include <cuda_bf16.h>
#include <math.h>

#define NN 50000
#define EE 800000
#define HH 64
#define LL 14
#define INF_ 128
#define OUTF 112
#define MSG_EPS 1e-7f
#define LN_EPS 1e-5f

// ---------------- scratch (static device globals; no allocation) ----------------
__device__ float g_h[NN * HH];     // current node features
__device__ float g_h2[NN * HH];    // relu(LN(h)) per layer
__device__ float g_agg[NN * HH];   // softmax aggregation result
__device__ int   g_deg[NN];
__device__ int   g_cur[NN];
__device__ int   g_off[NN + 1];
__device__ int   g_srt_src[EE];    // src indices bucketed by dst

// ---------------- CSR build ----------------
__global__ void k_zero() {
    int i = blockIdx.x * blockDim.x + threadIdx.x;
    if (i < NN) { g_deg[i] = 0; g_cur[i] = 0; }
}

__global__ void k_hist(const int* __restrict__ dst) {
    int e = blockIdx.x * blockDim.x + threadIdx.x;
    if (e < EE) atomicAdd(&g_deg[dst[e]], 1);
}

__global__ void k_scan() {
    __shared__ int part[1024];
    const int tid = threadIdx.x;
    const int CH = (NN + 1023) / 1024;  // 49
    int beg = tid * CH;
    int end = min(beg + CH, NN);
    int s = 0;
    for (int i = beg; i < end; i++) s += g_deg[i];
    part[tid] = s;
    __syncthreads();
    for (int off = 1; off < 1024; off <<= 1) {
        int v = 0;
        if (tid >= off) v = part[tid - off];
        __syncthreads();
        if (tid >= off) part[tid] += v;
        __syncthreads();
    }
    int run = part[tid] - s;
    for (int i = beg; i < end; i++) { g_off[i] = run; run += g_deg[i]; }
    if (tid == 1023) g_off[NN] = run;
}

__global__ void k_scatter(const int* __restrict__ src,
                          const int* __restrict__ dst) {
    int e = blockIdx.x * blockDim.x + threadIdx.x;
    if (e < EE) {
        int d = dst[e];
        int pos = g_off[d] + atomicAdd(&g_cur[d], 1);
        g_srt_src[pos] = src[e];
    }
}

// ---------------- encoder: h = x @ enc_W + enc_b  ([N,128]@[128,64]) ----------------
__global__ void __launch_bounds__(256) k_enc(const float* __restrict__ x,
                                             const float* __restrict__ W,
                                             const float* __restrict__ b) {
    __shared__ float Ws[INF_ * HH];  // 32 KB
    __shared__ float xs[4][INF_];
    int tid = threadIdx.x;
    int nl = tid >> 6, j = tid & 63;
    for (int i = tid; i < INF_ * HH; i += 256) Ws[i] = W[i];
    int n = blockIdx.x * 4 + nl;
    if (n < NN) {
        xs[nl][j]      = x[n * INF_ + j];
        xs[nl][j + 64] = x[n * INF_ + j + 64];
    }
    __syncthreads();
    if (n < NN) {
        float acc = b[j];
        #pragma unroll
        for (int k = 0; k < INF_; k++) acc = fmaf(xs[nl][k], Ws[k * HH + j], acc);
        g_h[n * HH + j] = acc;
    }
}

// ---------------- LayerNorm + ReLU: g_h2 = relu(LN(g_h)) ----------------
__global__ void __launch_bounds__(256) k_ln(const float* __restrict__ gma,
                                            const float* __restrict__ bta) {
    int warp = (blockIdx.x * blockDim.x + threadIdx.x) >> 5;
    int lane = threadIdx.x & 31;
    if (warp >= NN) return;
    float2 v = *(const float2*)(g_h + warp * HH + lane * 2);
    float s = v.x + v.y;
    #pragma unroll
    for (int o = 16; o; o >>= 1) s += __shfl_xor_sync(0xffffffffu, s, o);
    float mu = s * (1.f / 64.f);
    float dx = v.x - mu, dy = v.y - mu;
    float vs = dx * dx + dy * dy;
    #pragma unroll
    for (int o = 16; o; o >>= 1) vs += __shfl_xor_sync(0xffffffffu, vs, o);
    float rs = rsqrtf(vs * (1.f / 64.f) + LN_EPS);
    float2 gg = *(const float2*)(gma + lane * 2);
    float2 bb = *(const float2*)(bta + lane * 2);
    float2 o2;
    o2.x = fmaxf(fmaf(dx * rs, gg.x, bb.x), 0.f);
    o2.y = fmaxf(fmaf(dy * rs, gg.y, bb.y), 0.f);
    *(float2*)(g_h2 + warp * HH + lane * 2) = o2;
}

// ---------------- softmax aggregation, SINGLE PASS, warp per node ----------------
// msg = relu(.)+eps is bounded (<= ~8 after LN, <= ~4 at layer 0), so exp cannot
// overflow and the max-shift is mathematically redundant:
//   agg = sum(m * e^m) / sum(e^m)
// Loop shape identical to the R2 pass (uniform broadcast index load per edge)
// which the compiler software-pipelines well.
__global__ void __launch_bounds__(256) k_agg(int use_h2) {
    const float* __restrict__ hsrc = use_h2 ? g_h2 : g_h;
    int warp = (blockIdx.x * blockDim.x + threadIdx.x) >> 5;
    int lane = threadIdx.x & 31;
    if (warp >= NN) return;
    int beg = g_off[warp], end = g_off[warp + 1];
    float d0 = 0.f, d1 = 0.f, n0 = 0.f, n1 = 0.f;
    for (int e = beg; e < end; e++) {
        int s = g_srt_src[e];   // same address for all lanes: broadcast, 1 sector
        float2 v = *(const float2*)(hsrc + s * HH + lane * 2);
        float m0 = fmaxf(v.x, 0.f) + MSG_EPS;
        float m1 = fmaxf(v.y, 0.f) + MSG_EPS;
        float e0 = __expf(m0);
        float e1 = __expf(m1);
        d0 += e0; n0 = fmaf(m0, e0, n0);
        d1 += e1; n1 = fmaf(m1, e1, n1);
    }
    float2 o;
    o.x = n0 / fmaxf(d0, 1e-16f);   // empty segment -> 0, matches reference
    o.y = n1 / fmaxf(d1, 1e-16f);
    *(float2*)(g_agg + warp * HH + lane * 2) = o;
}

// ---------------- combine + 64x64 GEMM: g_h = (base + agg) @ W + b [+ g_h] ----------------
__global__ void __launch_bounds__(256) k_mat(const float* __restrict__ W,
                                             const float* __restrict__ b,
                                             int use_h2, int res) {
    __shared__ float Ws[HH * HH];  // 16 KB
    __shared__ float ts[4][HH];
    int tid = threadIdx.x;
    int nl = tid >> 6, j = tid & 63;
    for (int i = tid; i < HH * HH; i += 256) Ws[i] = W[i];
    int n = blockIdx.x * 4 + nl;
    float t = 0.f;
    if (n < NN) {
        const float* base = use_h2 ? g_h2 : g_h;
        t = base[n * HH + j] + g_agg[n * HH + j];
    }
    ts[nl][j] = t;
    __syncthreads();
    if (n < NN) {
        float acc = b[j] + (res ? g_h[n * HH + j] : 0.f);
        #pragma unroll
        for (int k = 0; k < HH; k++) acc = fmaf(ts[nl][k], Ws[k * HH + j], acc);
        g_h[n * HH + j] = acc;
    }
}

// ---------------- predictor: out = h @ pred_W + pred_b ([N,64]@[64,112]) ----------------
__global__ void __launch_bounds__(224) k_pred(const float* __restrict__ W,
                                              const float* __restrict__ b,
                                              float* __restrict__ out) {
    __shared__ float Ws[HH * OUTF];  // 28 KB
    __shared__ float hs[2][HH];
    int tid = threadIdx.x;
    for (int i = tid; i < HH * OUTF; i += 224) Ws[i] = W[i];
    if (tid < 128) {
        int nl = tid >> 6, k = tid & 63;
        int n = blockIdx.x * 2 + nl;
        hs[nl][k] = (n < NN) ? g_h[n * HH + k] : 0.f;
    }
    __syncthreads();
    int nl = tid / OUTF, j = tid % OUTF;
    int n = blockIdx.x * 2 + nl;
    if (n < NN) {
        float acc = b[j];
        #pragma unroll
        for (int k = 0; k < HH; k++) acc = fmaf(hs[nl][k], Ws[k * OUTF + j], acc);
        out[n * OUTF + j] = acc;
    }
}

// ---------------- launch ----------------
extern "C" void kernel_launch(void* const* d_in, const int* in_sizes, int n_in,
                              void* d_out, int out_size) {
    const float* x      = (const float*)d_in[0];
    const int*   ei     = (const int*)d_in[1];   // int32 (jax x64 disabled)
    const float* enc_W  = (const float*)d_in[2];
    const float* enc_b  = (const float*)d_in[3];
    const float* ln_g   = (const float*)d_in[4];
    const float* ln_b   = (const float*)d_in[5];
    const float* mlp_W  = (const float*)d_in[6];
    const float* mlp_b  = (const float*)d_in[7];
    const float* pred_W = (const float*)d_in[8];
    const float* pred_b = (const float*)d_in[9];
    float*       out    = (float*)d_out;

    const int* src = ei;
    const int* dst = ei + EE;

    // CSR build (counting sort by dst)
    k_zero<<<(NN + 255) / 256, 256>>>();
    k_hist<<<(EE + 255) / 256, 256>>>(dst);
    k_scan<<<1, 1024>>>();
    k_scatter<<<(EE + 255) / 256, 256>>>(src, dst);

    // encoder
    k_enc<<<(NN + 3) / 4, 256>>>(x, enc_W, enc_b);

    const int agg_blocks = (NN * 32 + 255) / 256;  // warp per node

    // layer 0: no pre-norm, no residual
    k_agg<<<agg_blocks, 256>>>(0);
    k_mat<<<(NN + 3) / 4, 256>>>(mlp_W, mlp_b, /*use_h2=*/0, /*res=*/0);

    // layers 1..13: h2 = relu(LN(h)); h = genconv(h2) + h
    for (int i = 1; i < LL; i++) {
        k_ln<<<(NN * 32 + 255) / 256, 256>>>(ln_g + (i - 1) * HH, ln_b + (i - 1) * HH);
        k_agg<<<agg_blocks, 256>>>(1);
        k_mat<<<(NN + 3) / 4, 256>>>(mlp_W + i * HH * HH, mlp_b + i * HH, 1, 1);
    }

    // predictor
    k_pred<<<(NN + 1) / 2, 224>>>(pred_W, pred_b, out);
}

// round 5
// speedup vs baseline: 2.0478x; 1.4744x over previous
#include <cuda_runtime.h>
#include <cuda_bf16.h>
#include <math.h>

#define NN 50000
#define EE 800000
#define HH 64
#define LL 14
#define INF_ 128
#define OUTF 112
#define MSG_EPS 1e-7f
#define LN_EPS 1e-5f

// ---------------- scratch (static device globals; no allocation) ----------------
__device__ float g_h[NN * HH];     // current node features
__device__ float g_h2[NN * HH];    // relu(LN(h)) per layer
__device__ float g_agg[NN * HH];   // softmax aggregation result
__device__ int   g_deg[NN];
__device__ int   g_cur[NN];
__device__ int   g_off[NN + 1];
__device__ int   g_srt_src[EE];    // src indices bucketed by dst

// ---------------- CSR build ----------------
__global__ void k_zero() {
    int i = blockIdx.x * blockDim.x + threadIdx.x;
    if (i < NN) { g_deg[i] = 0; g_cur[i] = 0; }
}

__global__ void k_hist(const int* __restrict__ dst) {
    int e = blockIdx.x * blockDim.x + threadIdx.x;
    if (e < EE) atomicAdd(&g_deg[dst[e]], 1);
}

__global__ void k_scan() {
    __shared__ int part[1024];
    const int tid = threadIdx.x;
    const int CH = (NN + 1023) / 1024;  // 49
    int beg = tid * CH;
    int end = min(beg + CH, NN);
    int s = 0;
    for (int i = beg; i < end; i++) s += g_deg[i];
    part[tid] = s;
    __syncthreads();
    for (int off = 1; off < 1024; off <<= 1) {
        int v = 0;
        if (tid >= off) v = part[tid - off];
        __syncthreads();
        if (tid >= off) part[tid] += v;
        __syncthreads();
    }
    int run = part[tid] - s;
    for (int i = beg; i < end; i++) { g_off[i] = run; run += g_deg[i]; }
    if (tid == 1023) g_off[NN] = run;
}

__global__ void k_scatter(const int* __restrict__ src,
                          const int* __restrict__ dst) {
    int e = blockIdx.x * blockDim.x + threadIdx.x;
    if (e < EE) {
        int d = dst[e];
        int pos = g_off[d] + atomicAdd(&g_cur[d], 1);
        g_srt_src[pos] = src[e];
    }
}

// ---------------- encoder: h = x @ enc_W + enc_b  (16 nodes/block, reg-blocked) ----------------
__global__ void __launch_bounds__(256) k_enc(const float* __restrict__ x,
                                             const float* __restrict__ W,
                                             const float* __restrict__ b) {
    __shared__ float Ws[INF_ * HH];   // 32 KB
    __shared__ float xs[16][INF_];    // 8 KB
    int tid = threadIdx.x;
    int nl = tid >> 6, j = tid & 63;
    int n0 = blockIdx.x * 16;
    for (int i = tid; i < INF_ * HH; i += 256) Ws[i] = W[i];
    for (int i = tid; i < 16 * INF_; i += 256) {
        int node = i >> 7, f = i & 127;
        xs[node][f] = (n0 + node < NN) ? x[(n0 + node) * INF_ + f] : 0.f;
    }
    __syncthreads();
    float bj = b[j];
    float acc[4] = {bj, bj, bj, bj};
    #pragma unroll
    for (int k = 0; k < INF_; k++) {
        float w = Ws[k * HH + j];
        #pragma unroll
        for (int i = 0; i < 4; i++) acc[i] = fmaf(xs[nl + 4 * i][k], w, acc[i]);
    }
    #pragma unroll
    for (int i = 0; i < 4; i++) {
        int n = n0 + nl + 4 * i;
        if (n < NN) g_h[n * HH + j] = acc[i];
    }
}

// ---------------- LayerNorm + ReLU: g_h2 = relu(LN(g_h)) ----------------
__global__ void __launch_bounds__(256) k_ln(const float* __restrict__ gma,
                                            const float* __restrict__ bta) {
    int warp = (blockIdx.x * blockDim.x + threadIdx.x) >> 5;
    int lane = threadIdx.x & 31;
    if (warp >= NN) return;
    float2 v = *(const float2*)(g_h + warp * HH + lane * 2);
    float s = v.x + v.y;
    #pragma unroll
    for (int o = 16; o; o >>= 1) s += __shfl_xor_sync(0xffffffffu, s, o);
    float mu = s * (1.f / 64.f);
    float dx = v.x - mu, dy = v.y - mu;
    float vs = dx * dx + dy * dy;
    #pragma unroll
    for (int o = 16; o; o >>= 1) vs += __shfl_xor_sync(0xffffffffu, vs, o);
    float rs = rsqrtf(vs * (1.f / 64.f) + LN_EPS);
    float2 gg = *(const float2*)(gma + lane * 2);
    float2 bb = *(const float2*)(bta + lane * 2);
    float2 o2;
    o2.x = fmaxf(fmaf(dx * rs, gg.x, bb.x), 0.f);
    o2.y = fmaxf(fmaf(dy * rs, gg.y, bb.y), 0.f);
    *(float2*)(g_h2 + warp * HH + lane * 2) = o2;
}

// ---------------- softmax aggregation, SINGLE PASS, warp per node ----------------
// msg = relu(.)+eps is bounded (<= ~8 after LN), so exp cannot overflow and the
// max-shift is mathematically redundant: agg = sum(m*e^m)/sum(e^m).
__global__ void __launch_bounds__(256) k_agg(int use_h2) {
    const float* __restrict__ hsrc = use_h2 ? g_h2 : g_h;
    int warp = (blockIdx.x * blockDim.x + threadIdx.x) >> 5;
    int lane = threadIdx.x & 31;
    if (warp >= NN) return;
    int beg = g_off[warp], end = g_off[warp + 1];
    float d0 = 0.f, d1 = 0.f, n0 = 0.f, n1 = 0.f;
    for (int e = beg; e < end; e++) {
        int s = g_srt_src[e];   // same address for all lanes: broadcast, 1 sector
        float2 v = *(const float2*)(hsrc + s * HH + lane * 2);
        float m0 = fmaxf(v.x, 0.f) + MSG_EPS;
        float m1 = fmaxf(v.y, 0.f) + MSG_EPS;
        float e0 = __expf(m0);
        float e1 = __expf(m1);
        d0 += e0; n0 = fmaf(m0, e0, n0);
        d1 += e1; n1 = fmaf(m1, e1, n1);
    }
    float2 o;
    o.x = n0 / fmaxf(d0, 1e-16f);   // empty segment -> 0, matches reference
    o.y = n1 / fmaxf(d1, 1e-16f);
    *(float2*)(g_agg + warp * HH + lane * 2) = o;
}

// ---------------- combine + 64x64 GEMM (32 nodes/block, reg-blocked) ----------------
// g_h[n] = (base[n] + agg[n]) @ W + b [+ g_h[n]]
__global__ void __launch_bounds__(256) k_mat(const float* __restrict__ W,
                                             const float* __restrict__ b,
                                             int use_h2, int res) {
    __shared__ float Ws[HH * HH];   // 16 KB
    __shared__ float ts[32][HH];    // 8 KB
    int tid = threadIdx.x;
    int nl = tid >> 6, j = tid & 63;
    int n0 = blockIdx.x * 32;
    const float* base = use_h2 ? g_h2 : g_h;
    for (int i = tid; i < HH * HH; i += 256) Ws[i] = W[i];
    for (int i = tid; i < 32 * HH; i += 256) {
        int node = i >> 6, f = i & 63;
        int n = n0 + node;
        ts[node][f] = (n < NN) ? base[n * HH + f] + g_agg[n * HH + f] : 0.f;
    }
    __syncthreads();
    float bj = b[j];
    float acc[8];
    #pragma unroll
    for (int i = 0; i < 8; i++) {
        int n = n0 + nl + 4 * i;
        acc[i] = bj + ((res && n < NN) ? g_h[n * HH + j] : 0.f);
    }
    #pragma unroll
    for (int k = 0; k < HH; k++) {
        float w = Ws[k * HH + j];
        #pragma unroll
        for (int i = 0; i < 8; i++) acc[i] = fmaf(ts[nl + 4 * i][k], w, acc[i]);
    }
    #pragma unroll
    for (int i = 0; i < 8; i++) {
        int n = n0 + nl + 4 * i;
        if (n < NN) g_h[n * HH + j] = acc[i];
    }
}

// ---------------- predictor: out = h @ pred_W + pred_b (16 nodes/block, reg-blocked) ----------------
__global__ void __launch_bounds__(224) k_pred(const float* __restrict__ W,
                                              const float* __restrict__ b,
                                              float* __restrict__ out) {
    __shared__ float Ws[HH * OUTF];  // 28 KB
    __shared__ float hs[16][HH];     // 4 KB
    int tid = threadIdx.x;
    int nl = tid / OUTF, j = tid % OUTF;   // nl in 0..1
    int n0 = blockIdx.x * 16;
    for (int i = tid; i < HH * OUTF; i += 224) Ws[i] = W[i];
    for (int i = tid; i < 16 * HH; i += 224) {
        int node = i >> 6, f = i & 63;
        int n = n0 + node;
        hs[node][f] = (n < NN) ? g_h[n * HH + f] : 0.f;
    }
    __syncthreads();
    float bj = b[j];
    float acc[8];
    #pragma unroll
    for (int i = 0; i < 8; i++) acc[i] = bj;
    #pragma unroll
    for (int k = 0; k < HH; k++) {
        float w = Ws[k * OUTF + j];
        #pragma unroll
        for (int i = 0; i < 8; i++) acc[i] = fmaf(hs[nl + 2 * i][k], w, acc[i]);
    }
    #pragma unroll
    for (int i = 0; i < 8; i++) {
        int n = n0 + nl + 2 * i;
        if (n < NN) out[n * OUTF + j] = acc[i];
    }
}

// ---------------- launch ----------------
extern "C" void kernel_launch(void* const* d_in, const int* in_sizes, int n_in,
                              void* d_out, int out_size) {
    const float* x      = (const float*)d_in[0];
    const int*   ei     = (const int*)d_in[1];   // int32 (jax x64 disabled)
    const float* enc_W  = (const float*)d_in[2];
    const float* enc_b  = (const float*)d_in[3];
    const float* ln_g   = (const float*)d_in[4];
    const float* ln_b   = (const float*)d_in[5];
    const float* mlp_W  = (const float*)d_in[6];
    const float* mlp_b  = (const float*)d_in[7];
    const float* pred_W = (const float*)d_in[8];
    const float* pred_b = (const float*)d_in[9];
    float*       out    = (float*)d_out;

    const int* src = ei;
    const int* dst = ei + EE;

    // CSR build (counting sort by dst)
    k_zero<<<(NN + 255) / 256, 256>>>();
    k_hist<<<(EE + 255) / 256, 256>>>(dst);
    k_scan<<<1, 1024>>>();
    k_scatter<<<(EE + 255) / 256, 256>>>(src, dst);

    // encoder
    k_enc<<<(NN + 15) / 16, 256>>>(x, enc_W, enc_b);

    const int agg_blocks = (NN * 32 + 255) / 256;  // warp per node
    const int mat_blocks = (NN + 31) / 32;

    // layer 0: no pre-norm, no residual
    k_agg<<<agg_blocks, 256>>>(0);
    k_mat<<<mat_blocks, 256>>>(mlp_W, mlp_b, /*use_h2=*/0, /*res=*/0);

    // layers 1..13: h2 = relu(LN(h)); h = genconv(h2) + h
    for (int i = 1; i < LL; i++) {
        k_ln<<<(NN * 32 + 255) / 256, 256>>>(ln_g + (i - 1) * HH, ln_b + (i - 1) * HH);
        k_agg<<<agg_blocks, 256>>>(1);
        k_mat<<<mat_blocks, 256>>>(mlp_W + i * HH * HH, mlp_b + i * HH, 1, 1);
    }

    // predictor
    k_pred<<<(NN + 15) / 16, 224>>>(pred_W, pred_b, out);
}

// round 7
// speedup vs baseline: 2.1790x; 1.0641x over previous
#include <cuda_runtime.h>
#include <math.h>

#define NN 50000
#define EE 800000
#define HH 64
#define LL 14
#define INF_ 128
#define OUTF 112
#define MSG_EPS 1e-7f
#define LN_EPS 1e-5f

// ---------------- scratch (static device globals; no allocation) ----------------
__device__ float g_h[NN * HH];      // residual stream (fp32)
__device__ float g_bufA[NN * HH];   // ping-pong gather/base source
__device__ float g_bufB[NN * HH];
__device__ int   g_deg[NN];
__device__ int   g_cur[NN];
__device__ int   g_off[NN + 1];
__device__ int   g_srt_src[EE];     // src indices bucketed by dst

// ---------------- CSR build ----------------
__global__ void k_zero() {
    int i = blockIdx.x * blockDim.x + threadIdx.x;
    if (i < NN) { g_deg[i] = 0; g_cur[i] = 0; }
}

__global__ void k_hist(const int* __restrict__ dst) {
    int e = blockIdx.x * blockDim.x + threadIdx.x;
    if (e < EE) atomicAdd(&g_deg[dst[e]], 1);
}

__global__ void k_scan() {
    __shared__ int part[1024];
    const int tid = threadIdx.x;
    const int CH = (NN + 1023) / 1024;  // 49
    int beg = tid * CH;
    int end = min(beg + CH, NN);
    int s = 0;
    for (int i = beg; i < end; i++) s += g_deg[i];
    part[tid] = s;
    __syncthreads();
    for (int off = 1; off < 1024; off <<= 1) {
        int v = 0;
        if (tid >= off) v = part[tid - off];
        __syncthreads();
        if (tid >= off) part[tid] += v;
        __syncthreads();
    }
    int run = part[tid] - s;
    for (int i = beg; i < end; i++) { g_off[i] = run; run += g_deg[i]; }
    if (tid == 1023) g_off[NN] = run;
}

__global__ void k_scatter(const int* __restrict__ src,
                          const int* __restrict__ dst) {
    int e = blockIdx.x * blockDim.x + threadIdx.x;
    if (e < EE) {
        int d = dst[e];
        int pos = g_off[d] + atomicAdd(&g_cur[d], 1);
        g_srt_src[pos] = src[e];
    }
}

// ---------------- encoder: h = x @ enc_W + enc_b -> g_h and g_bufA ----------------
__global__ void __launch_bounds__(256) k_enc(const float* __restrict__ x,
                                             const float* __restrict__ W,
                                             const float* __restrict__ b) {
    __shared__ float Ws[INF_ * HH];   // 32 KB
    __shared__ float xs[16][INF_];    // 8 KB
    int tid = threadIdx.x;
    int nl = tid >> 6, j = tid & 63;
    int n0 = blockIdx.x * 16;
    for (int i = tid; i < INF_ * HH; i += 256) Ws[i] = W[i];
    for (int i = tid; i < 16 * INF_; i += 256) {
        int node = i >> 7, f = i & 127;
        xs[node][f] = (n0 + node < NN) ? x[(n0 + node) * INF_ + f] : 0.f;
    }
    __syncthreads();
    float bj = b[j];
    float acc[4] = {bj, bj, bj, bj};
    #pragma unroll
    for (int k = 0; k < INF_; k++) {
        float w = Ws[k * HH + j];
        #pragma unroll
        for (int i = 0; i < 4; i++) acc[i] = fmaf(xs[nl + 4 * i][k], w, acc[i]);
    }
    #pragma unroll
    for (int i = 0; i < 4; i++) {
        int n = n0 + nl + 4 * i;
        if (n < NN) {
            g_h[n * HH + j] = acc[i];
            g_bufA[n * HH + j] = acc[i];   // read-only gather source for layer 0
        }
    }
}

// ---------------- fused layer kernel (32 nodes/block) ----------------
// phase A: warp-per-node single-pass softmax aggregation over gsrc + base(gsrc) -> smem
// phase B: reg-blocked 64x64 GEMM + bias + optional residual -> g_h (+ smem)
// phase C: warp-per-node LayerNorm+ReLU -> gdst (next layer's gather source)
// gsrc is never written in this launch (ping-pong) -> no cross-block race.
__global__ void __launch_bounds__(256) k_layer(const float* __restrict__ W,
                                               const float* __restrict__ b,
                                               const float* __restrict__ gma,
                                               const float* __restrict__ bta,
                                               const float* __restrict__ gsrc,
                                               float* __restrict__ gdst,
                                               int res, int write_h2) {
    __shared__ float Ws[HH * HH];   // 16 KB
    __shared__ float ts[32][HH];    // 8 KB
    int tid = threadIdx.x;
    int wid = tid >> 5, lane = tid & 31;
    int nl = tid >> 6, j = tid & 63;
    int n0 = blockIdx.x * 32;

    for (int i = tid; i < HH * HH; i += 256) Ws[i] = W[i];

    // ---- phase A: aggregation (msg bounded after LN/enc => single-pass softmax safe) ----
    #pragma unroll
    for (int i = 0; i < 4; i++) {
        int nb = wid * 4 + i;
        int n = n0 + nb;
        if (n < NN) {
            int beg = g_off[n], end = g_off[n + 1];
            float d0 = 0.f, d1 = 0.f, s0 = 0.f, s1 = 0.f;
            for (int e = beg; e < end; e++) {
                int s = g_srt_src[e];                 // uniform broadcast load
                float2 v = *(const float2*)(gsrc + s * HH + lane * 2);
                float m0 = fmaxf(v.x, 0.f) + MSG_EPS;
                float m1 = fmaxf(v.y, 0.f) + MSG_EPS;
                float e0 = __expf(m0);
                float e1 = __expf(m1);
                d0 += e0; s0 = fmaf(m0, e0, s0);
                d1 += e1; s1 = fmaf(m1, e1, s1);
            }
            float2 base2 = *(const float2*)(gsrc + n * HH + lane * 2);
            float2 o;
            o.x = base2.x + s0 / fmaxf(d0, 1e-16f);   // empty segment -> +0
            o.y = base2.y + s1 / fmaxf(d1, 1e-16f);
            *(float2*)(&ts[nb][lane * 2]) = o;
        }
    }
    __syncthreads();

    // ---- phase B: GEMM (reg-blocked, 8 nodes/thread) + residual ----
    float bj = b[j];
    float acc[8];
    #pragma unroll
    for (int i = 0; i < 8; i++) {
        int n = n0 + nl + 4 * i;
        acc[i] = bj + ((res && n < NN) ? g_h[n * HH + j] : 0.f);
    }
    #pragma unroll
    for (int k = 0; k < HH; k++) {
        float w = Ws[k * HH + j];
        #pragma unroll
        for (int i = 0; i < 8; i++) acc[i] = fmaf(ts[nl + 4 * i][k], w, acc[i]);
    }
    __syncthreads();   // everyone done reading ts before overwrite
    #pragma unroll
    for (int i = 0; i < 8; i++) {
        int n = n0 + nl + 4 * i;
        if (n < NN) g_h[n * HH + j] = acc[i];
        ts[nl + 4 * i][j] = acc[i];
    }

    // ---- phase C: LayerNorm + ReLU -> gdst ----
    if (!write_h2) return;
    __syncthreads();
    float2 gg = *(const float2*)(gma + lane * 2);
    float2 bb = *(const float2*)(bta + lane * 2);
    #pragma unroll
    for (int i = 0; i < 4; i++) {
        int nb = wid * 4 + i;
        int n = n0 + nb;
        if (n >= NN) continue;
        float2 v = *(const float2*)(&ts[nb][lane * 2]);
        float s = v.x + v.y;
        #pragma unroll
        for (int o = 16; o; o >>= 1) s += __shfl_xor_sync(0xffffffffu, s, o);
        float mu = s * (1.f / 64.f);
        float dx = v.x - mu, dy = v.y - mu;
        float vs = dx * dx + dy * dy;
        #pragma unroll
        for (int o = 16; o; o >>= 1) vs += __shfl_xor_sync(0xffffffffu, vs, o);
        float rs = rsqrtf(vs * (1.f / 64.f) + LN_EPS);
        float2 o2;
        o2.x = fmaxf(fmaf(dx * rs, gg.x, bb.x), 0.f);
        o2.y = fmaxf(fmaf(dy * rs, gg.y, bb.y), 0.f);
        *(float2*)(gdst + n * HH + lane * 2) = o2;
    }
}

// ---------------- predictor: out = h @ pred_W + pred_b (16 nodes/block, reg-blocked) ----------------
__global__ void __launch_bounds__(224) k_pred(const float* __restrict__ W,
                                              const float* __restrict__ b,
                                              float* __restrict__ out) {
    __shared__ float Ws[HH * OUTF];  // 28 KB
    __shared__ float hs[16][HH];     // 4 KB
    int tid = threadIdx.x;
    int nl = tid / OUTF, j = tid % OUTF;   // nl in 0..1
    int n0 = blockIdx.x * 16;
    for (int i = tid; i < HH * OUTF; i += 224) Ws[i] = W[i];
    for (int i = tid; i < 16 * HH; i += 224) {
        int node = i >> 6, f = i & 63;
        int n = n0 + node;
        hs[node][f] = (n < NN) ? g_h[n * HH + f] : 0.f;
    }
    __syncthreads();
    float bj = b[j];
    float acc[8];
    #pragma unroll
    for (int i = 0; i < 8; i++) acc[i] = bj;
    #pragma unroll
    for (int k = 0; k < HH; k++) {
        float w = Ws[k * OUTF + j];
        #pragma unroll
        for (int i = 0; i < 8; i++) acc[i] = fmaf(hs[nl + 2 * i][k], w, acc[i]);
    }
    #pragma unroll
    for (int i = 0; i < 8; i++) {
        int n = n0 + nl + 2 * i;
        if (n < NN) out[n * OUTF + j] = acc[i];
    }
}

// ---------------- launch ----------------
extern "C" void kernel_launch(void* const* d_in, const int* in_sizes, int n_in,
                              void* d_out, int out_size) {
    const float* x      = (const float*)d_in[0];
    const int*   ei     = (const int*)d_in[1];   // int32 (jax x64 disabled)
    const float* enc_W  = (const float*)d_in[2];
    const float* enc_b  = (const float*)d_in[3];
    const float* ln_g   = (const float*)d_in[4];
    const float* ln_b   = (const float*)d_in[5];
    const float* mlp_W  = (const float*)d_in[6];
    const float* mlp_b  = (const float*)d_in[7];
    const float* pred_W = (const float*)d_in[8];
    const float* pred_b = (const float*)d_in[9];
    float*       out    = (float*)d_out;

    const int* src = ei;
    const int* dst = ei + EE;

    // CSR build (counting sort by dst)
    k_zero<<<(NN + 255) / 256, 256>>>();
    k_hist<<<(EE + 255) / 256, 256>>>(dst);
    k_scan<<<1, 1024>>>();
    k_scatter<<<(EE + 255) / 256, 256>>>(src, dst);

    // encoder (g_h + g_bufA copy for layer-0 gathers)
    k_enc<<<(NN + 15) / 16, 256>>>(x, enc_W, enc_b);

    const int blocks = (NN + 31) / 32;

    float* bufA = nullptr;
    float* bufB = nullptr;
    cudaGetSymbolAddress((void**)&bufA, g_bufA);
    cudaGetSymbolAddress((void**)&bufB, g_bufB);

    // layer i: gather/base from buf[i%2], LN output to buf[(i+1)%2]
    for (int i = 0; i < LL; i++) {
        const float* gsrc = (i & 1) ? bufB : bufA;
        float*       gdst = (i & 1) ? bufA : bufB;
        k_layer<<<blocks, 256>>>(mlp_W + i * HH * HH, mlp_b + i * HH,
                                 ln_g + i * HH, ln_b + i * HH,
                                 gsrc, gdst,
                                 /*res=*/(i > 0) ? 1 : 0,
                                 /*write_h2=*/(i < LL - 1) ? 1 : 0);
    }

    // predictor
    k_pred<<<(NN + 15) / 16, 224>>>(pred_W, pred_b, out);
}

// round 8
// speedup vs baseline: 2.1840x; 1.0023x over previous
#include <cuda_runtime.h>
#include <cuda_fp16.h>
#include <math.h>

#define NN 50000
#define EE 800000
#define HH 64
#define LL 14
#define INF_ 128
#define OUTF 112
#define MSG_EPS 1e-7f
#define LN_EPS 1e-5f

// ---------------- scratch (static device globals; no allocation) ----------------
__device__ float  g_h[NN * HH];      // residual stream (fp32)
__device__ float  g_bufA[NN * HH];   // ping-pong base source (fp32, self reads)
__device__ float  g_bufB[NN * HH];
__device__ __half g_hhA[NN * HH];    // ping-pong gather source (half, neighbor reads)
__device__ __half g_hhB[NN * HH];
__device__ int    g_deg[NN];
__device__ int    g_cur[NN];
__device__ int    g_off[NN + 1];
__device__ int    g_srt_src[EE];     // src indices bucketed by dst

// ---------------- CSR build ----------------
__global__ void k_zero() {
    int i = blockIdx.x * blockDim.x + threadIdx.x;
    if (i < NN) { g_deg[i] = 0; g_cur[i] = 0; }
}

__global__ void k_hist(const int* __restrict__ dst) {
    int e = blockIdx.x * blockDim.x + threadIdx.x;
    if (e < EE) atomicAdd(&g_deg[dst[e]], 1);
}

__global__ void k_scan() {
    __shared__ int part[1024];
    const int tid = threadIdx.x;
    const int CH = (NN + 1023) / 1024;  // 49
    int beg = tid * CH;
    int end = min(beg + CH, NN);
    int s = 0;
    for (int i = beg; i < end; i++) s += g_deg[i];
    part[tid] = s;
    __syncthreads();
    for (int off = 1; off < 1024; off <<= 1) {
        int v = 0;
        if (tid >= off) v = part[tid - off];
        __syncthreads();
        if (tid >= off) part[tid] += v;
        __syncthreads();
    }
    int run = part[tid] - s;
    for (int i = beg; i < end; i++) { g_off[i] = run; run += g_deg[i]; }
    if (tid == 1023) g_off[NN] = run;
}

__global__ void k_scatter(const int* __restrict__ src,
                          const int* __restrict__ dst) {
    int e = blockIdx.x * blockDim.x + threadIdx.x;
    if (e < EE) {
        int d = dst[e];
        int pos = g_off[d] + atomicAdd(&g_cur[d], 1);
        g_srt_src[pos] = src[e];
    }
}

// ---------------- encoder: h = x @ enc_W + enc_b -> g_h, g_bufA (fp32), g_hhA (half) ----------------
__global__ void __launch_bounds__(256) k_enc(const float* __restrict__ x,
                                             const float* __restrict__ W,
                                             const float* __restrict__ b) {
    __shared__ float Ws[INF_ * HH];   // 32 KB
    __shared__ float xs[16][INF_];    // 8 KB
    int tid = threadIdx.x;
    int nl = tid >> 6, j = tid & 63;
    int n0 = blockIdx.x * 16;
    for (int i = tid; i < INF_ * HH; i += 256) Ws[i] = W[i];
    for (int i = tid; i < 16 * INF_; i += 256) {
        int node = i >> 7, f = i & 127;
        xs[node][f] = (n0 + node < NN) ? x[(n0 + node) * INF_ + f] : 0.f;
    }
    __syncthreads();
    float bj = b[j];
    float acc[4] = {bj, bj, bj, bj};
    #pragma unroll
    for (int k = 0; k < INF_; k++) {
        float w = Ws[k * HH + j];
        #pragma unroll
        for (int i = 0; i < 4; i++) acc[i] = fmaf(xs[nl + 4 * i][k], w, acc[i]);
    }
    #pragma unroll
    for (int i = 0; i < 4; i++) {
        int n = n0 + nl + 4 * i;
        if (n < NN) {
            g_h[n * HH + j] = acc[i];
            g_bufA[n * HH + j] = acc[i];                // layer-0 base (fp32)
            g_hhA[n * HH + j] = __float2half_rn(acc[i]); // layer-0 gather (half)
        }
    }
}

// ---------------- fused layer kernel (32 nodes/block) ----------------
// phase A: warp-per-node single-pass softmax aggregation; neighbors gathered in
//          half (hhsrc), self base in fp32 (gsrc) -> smem ts
// phase B: reg-blocked 64x64 GEMM + bias + optional residual -> g_h (+ smem)
// phase C: warp-per-node LayerNorm+ReLU -> gdst (fp32) + hhdst (half)
// All sources ping-ponged: nothing read this launch is written this launch.
__global__ void __launch_bounds__(256) k_layer(const float* __restrict__ W,
                                               const float* __restrict__ b,
                                               const float* __restrict__ gma,
                                               const float* __restrict__ bta,
                                               const float* __restrict__ gsrc,
                                               const __half2* __restrict__ hhsrc,
                                               float* __restrict__ gdst,
                                               __half2* __restrict__ hhdst,
                                               int res, int write_h2) {
    __shared__ float Ws[HH * HH];   // 16 KB
    __shared__ float ts[32][HH];    // 8 KB
    int tid = threadIdx.x;
    int wid = tid >> 5, lane = tid & 31;
    int nl = tid >> 6, j = tid & 63;
    int n0 = blockIdx.x * 32;

    for (int i = tid; i < HH * HH; i += 256) Ws[i] = W[i];

    // ---- phase A: aggregation (msg bounded => single-pass softmax safe) ----
    #pragma unroll
    for (int i = 0; i < 4; i++) {
        int nb = wid * 4 + i;
        int n = n0 + nb;
        if (n < NN) {
            int beg = g_off[n], end = g_off[n + 1];
            float d0 = 0.f, d1 = 0.f, s0 = 0.f, s1 = 0.f;
            for (int e = beg; e < end; e++) {
                int s = g_srt_src[e];                       // uniform broadcast load
                float2 v = __half22float2(hhsrc[s * 32 + lane]);  // 4 B/lane gather
                float m0 = fmaxf(v.x, 0.f) + MSG_EPS;
                float m1 = fmaxf(v.y, 0.f) + MSG_EPS;
                float e0 = __expf(m0);
                float e1 = __expf(m1);
                d0 += e0; s0 = fmaf(m0, e0, s0);
                d1 += e1; s1 = fmaf(m1, e1, s1);
            }
            float2 base2 = *(const float2*)(gsrc + n * HH + lane * 2);  // fp32 self
            float2 o;
            o.x = base2.x + s0 / fmaxf(d0, 1e-16f);   // empty segment -> +0
            o.y = base2.y + s1 / fmaxf(d1, 1e-16f);
            *(float2*)(&ts[nb][lane * 2]) = o;
        }
    }
    __syncthreads();

    // ---- phase B: GEMM (reg-blocked, 8 nodes/thread) + residual ----
    float bj = b[j];
    float acc[8];
    #pragma unroll
    for (int i = 0; i < 8; i++) {
        int n = n0 + nl + 4 * i;
        acc[i] = bj + ((res && n < NN) ? g_h[n * HH + j] : 0.f);
    }
    #pragma unroll
    for (int k = 0; k < HH; k++) {
        float w = Ws[k * HH + j];
        #pragma unroll
        for (int i = 0; i < 8; i++) acc[i] = fmaf(ts[nl + 4 * i][k], w, acc[i]);
    }
    __syncthreads();   // everyone done reading ts before overwrite
    #pragma unroll
    for (int i = 0; i < 8; i++) {
        int n = n0 + nl + 4 * i;
        if (n < NN) g_h[n * HH + j] = acc[i];
        ts[nl + 4 * i][j] = acc[i];
    }

    // ---- phase C: LayerNorm + ReLU -> gdst (fp32) + hhdst (half) ----
    if (!write_h2) return;
    __syncthreads();
    float2 gg = *(const float2*)(gma + lane * 2);
    float2 bb = *(const float2*)(bta + lane * 2);
    #pragma unroll
    for (int i = 0; i < 4; i++) {
        int nb = wid * 4 + i;
        int n = n0 + nb;
        if (n >= NN) continue;
        float2 v = *(const float2*)(&ts[nb][lane * 2]);
        float s = v.x + v.y;
        #pragma unroll
        for (int o = 16; o; o >>= 1) s += __shfl_xor_sync(0xffffffffu, s, o);
        float mu = s * (1.f / 64.f);
        float dx = v.x - mu, dy = v.y - mu;
        float vs = dx * dx + dy * dy;
        #pragma unroll
        for (int o = 16; o; o >>= 1) vs += __shfl_xor_sync(0xffffffffu, vs, o);
        float rs = rsqrtf(vs * (1.f / 64.f) + LN_EPS);
        float2 o2;
        o2.x = fmaxf(fmaf(dx * rs, gg.x, bb.x), 0.f);
        o2.y = fmaxf(fmaf(dy * rs, gg.y, bb.y), 0.f);
        *(float2*)(gdst + n * HH + lane * 2) = o2;
        hhdst[n * 32 + lane] = __float22half2_rn(o2);
    }
}

// ---------------- predictor: out = h @ pred_W + pred_b (16 nodes/block, reg-blocked) ----------------
__global__ void __launch_bounds__(224) k_pred(const float* __restrict__ W,
                                              const float* __restrict__ b,
                                              float* __restrict__ out) {
    __shared__ float Ws[HH * OUTF];  // 28 KB
    __shared__ float hs[16][HH];     // 4 KB
    int tid = threadIdx.x;
    int nl = tid / OUTF, j = tid % OUTF;   // nl in 0..1
    int n0 = blockIdx.x * 16;
    for (int i = tid; i < HH * OUTF; i += 224) Ws[i] = W[i];
    for (int i = tid; i < 16 * HH; i += 224) {
        int node = i >> 6, f = i & 63;
        int n = n0 + node;
        hs[node][f] = (n < NN) ? g_h[n * HH + f] : 0.f;
    }
    __syncthreads();
    float bj = b[j];
    float acc[8];
    #pragma unroll
    for (int i = 0; i < 8; i++) acc[i] = bj;
    #pragma unroll
    for (int k = 0; k < HH; k++) {
        float w = Ws[k * OUTF + j];
        #pragma unroll
        for (int i = 0; i < 8; i++) acc[i] = fmaf(hs[nl + 2 * i][k], w, acc[i]);
    }
    #pragma unroll
    for (int i = 0; i < 8; i++) {
        int n = n0 + nl + 2 * i;
        if (n < NN) out[n * OUTF + j] = acc[i];
    }
}

// ---------------- launch ----------------
extern "C" void kernel_launch(void* const* d_in, const int* in_sizes, int n_in,
                              void* d_out, int out_size) {
    const float* x      = (const float*)d_in[0];
    const int*   ei     = (const int*)d_in[1];   // int32 (jax x64 disabled)
    const float* enc_W  = (const float*)d_in[2];
    const float* enc_b  = (const float*)d_in[3];
    const float* ln_g   = (const float*)d_in[4];
    const float* ln_b   = (const float*)d_in[5];
    const float* mlp_W  = (const float*)d_in[6];
    const float* mlp_b  = (const float*)d_in[7];
    const float* pred_W = (const float*)d_in[8];
    const float* pred_b = (const float*)d_in[9];
    float*       out    = (float*)d_out;

    const int* src = ei;
    const int* dst = ei + EE;

    // CSR build (counting sort by dst)
    k_zero<<<(NN + 255) / 256, 256>>>();
    k_hist<<<(EE + 255) / 256, 256>>>(dst);
    k_scan<<<1, 1024>>>();
    k_scatter<<<(EE + 255) / 256, 256>>>(src, dst);

    // encoder (g_h + fp32 bufA + half hhA)
    k_enc<<<(NN + 15) / 16, 256>>>(x, enc_W, enc_b);

    const int blocks = (NN + 31) / 32;

    float *bufA = nullptr, *bufB = nullptr;
    __half *hhA = nullptr, *hhB = nullptr;
    cudaGetSymbolAddress((void**)&bufA, g_bufA);
    cudaGetSymbolAddress((void**)&bufB, g_bufB);
    cudaGetSymbolAddress((void**)&hhA, g_hhA);
    cudaGetSymbolAddress((void**)&hhB, g_hhB);

    // layer i: sources = buf/hh[i%2], LN outputs -> buf/hh[(i+1)%2]
    for (int i = 0; i < LL; i++) {
        const float*   gsrc  = (i & 1) ? bufB : bufA;
        float*         gdst  = (i & 1) ? bufA : bufB;
        const __half2* hhsrc = (const __half2*)((i & 1) ? hhB : hhA);
        __half2*       hhdst = (__half2*)((i & 1) ? hhA : hhB);
        k_layer<<<blocks, 256>>>(mlp_W + i * HH * HH, mlp_b + i * HH,
                                 ln_g + i * HH, ln_b + i * HH,
                                 gsrc, hhsrc, gdst, hhdst,
                                 /*res=*/(i > 0) ? 1 : 0,
                                 /*write_h2=*/(i < LL - 1) ? 1 : 0);
    }

    // predictor
    k_pred<<<(NN + 15) / 16, 224>>>(pred_W, pred_b, out);
}

// round 9
// speedup vs baseline: 2.2120x; 1.0128x over previous
#include <cuda_runtime.h>
#include <cuda_fp16.h>
#include <math.h>

#define NN 50000
#define EE 800000
#define HH 64
#define LL 14
#define INF_ 128
#define OUTF 112
#define MSG_EPS 1e-7f
#define LN_EPS 1e-5f

#define TILE 16                       // nodes per tile
#define NTILES ((NN + TILE - 1) / TILE)   // 3125
#define PGRID 1216                    // persistent grid (8 blocks/SM * 152 SMs)

// ---------------- scratch (static device globals; no allocation) ----------------
__device__ float  g_h[NN * HH];      // residual stream (fp32)
__device__ float  g_bufA[NN * HH];   // ping-pong base source (fp32, self reads)
__device__ float  g_bufB[NN * HH];
__device__ __half g_hhA[NN * HH];    // ping-pong gather source (half, neighbor reads)
__device__ __half g_hhB[NN * HH];
__device__ int    g_deg[NN];
__device__ int    g_cur[NN];
__device__ int    g_off[NN + 1];
__device__ int    g_srt_src[EE];     // src indices bucketed by dst

// ---------------- CSR build ----------------
__global__ void k_zero() {
    int i = blockIdx.x * blockDim.x + threadIdx.x;
    if (i < NN) { g_deg[i] = 0; g_cur[i] = 0; }
}

__global__ void k_hist(const int* __restrict__ dst) {
    int e = blockIdx.x * blockDim.x + threadIdx.x;
    if (e < EE) atomicAdd(&g_deg[dst[e]], 1);
}

__global__ void k_scan() {
    __shared__ int part[1024];
    const int tid = threadIdx.x;
    const int CH = (NN + 1023) / 1024;  // 49
    int beg = tid * CH;
    int end = min(beg + CH, NN);
    int s = 0;
    for (int i = beg; i < end; i++) s += g_deg[i];
    part[tid] = s;
    __syncthreads();
    for (int off = 1; off < 1024; off <<= 1) {
        int v = 0;
        if (tid >= off) v = part[tid - off];
        __syncthreads();
        if (tid >= off) part[tid] += v;
        __syncthreads();
    }
    int run = part[tid] - s;
    for (int i = beg; i < end; i++) { g_off[i] = run; run += g_deg[i]; }
    if (tid == 1023) g_off[NN] = run;
}

__global__ void k_scatter(const int* __restrict__ src,
                          const int* __restrict__ dst) {
    int e = blockIdx.x * blockDim.x + threadIdx.x;
    if (e < EE) {
        int d = dst[e];
        int pos = g_off[d] + atomicAdd(&g_cur[d], 1);
        g_srt_src[pos] = src[e];
    }
}

// ---------------- encoder: h = x @ enc_W + enc_b -> g_h, g_bufA (fp32), g_hhA (half) ----------------
__global__ void __launch_bounds__(256) k_enc(const float* __restrict__ x,
                                             const float* __restrict__ W,
                                             const float* __restrict__ b) {
    __shared__ float Ws[INF_ * HH];   // 32 KB
    __shared__ float xs[16][INF_];    // 8 KB
    int tid = threadIdx.x;
    int nl = tid >> 6, j = tid & 63;
    int n0 = blockIdx.x * 16;
    for (int i = tid; i < INF_ * HH; i += 256) Ws[i] = W[i];
    for (int i = tid; i < 16 * INF_; i += 256) {
        int node = i >> 7, f = i & 127;
        xs[node][f] = (n0 + node < NN) ? x[(n0 + node) * INF_ + f] : 0.f;
    }
    __syncthreads();
    float bj = b[j];
    float acc[4] = {bj, bj, bj, bj};
    #pragma unroll
    for (int k = 0; k < INF_; k++) {
        float w = Ws[k * HH + j];
        #pragma unroll
        for (int i = 0; i < 4; i++) acc[i] = fmaf(xs[nl + 4 * i][k], w, acc[i]);
    }
    #pragma unroll
    for (int i = 0; i < 4; i++) {
        int n = n0 + nl + 4 * i;
        if (n < NN) {
            g_h[n * HH + j] = acc[i];
            g_bufA[n * HH + j] = acc[i];                 // layer-0 base (fp32)
            g_hhA[n * HH + j] = __float2half_rn(acc[i]); // layer-0 gather (half)
        }
    }
}

// ---------------- fused persistent layer kernel ----------------
// Grid-stride over 16-node tiles. W in smem loaded once per block.
// phase A: warp-per-node (2 nodes/warp) single-pass softmax agg, fp16 gathers,
//          4x-unrolled edge loop for MLP; + fp32 self base -> smem ts
// phase B: reg-blocked 64x64 GEMM (4 nodes/thread) + bias + residual -> g_h
// phase C: LayerNorm+ReLU -> gdst (fp32) + hhdst (half)
__global__ void __launch_bounds__(256) k_layer(const float* __restrict__ W,
                                               const float* __restrict__ b,
                                               const float* __restrict__ gma,
                                               const float* __restrict__ bta,
                                               const float* __restrict__ gsrc,
                                               const __half2* __restrict__ hhsrc,
                                               float* __restrict__ gdst,
                                               __half2* __restrict__ hhdst,
                                               int res, int write_h2) {
    __shared__ float Ws[HH * HH];    // 16 KB
    __shared__ float ts[TILE][HH];   // 4 KB
    int tid = threadIdx.x;
    int wid = tid >> 5, lane = tid & 31;
    int nl = tid >> 6, j = tid & 63;

    for (int i = tid; i < HH * HH; i += 256) Ws[i] = W[i];
    float bj = b[j];
    float2 gg = *(const float2*)(gma + lane * 2);
    float2 bb = *(const float2*)(bta + lane * 2);

    for (int tile = blockIdx.x; tile < NTILES; tile += PGRID) {
        int n0 = tile * TILE;
        __syncthreads();   // Ws ready (1st iter) / prev phase C done with ts

        // ---- phase A: aggregation, 2 nodes per warp ----
        #pragma unroll
        for (int i = 0; i < 2; i++) {
            int nb = wid * 2 + i;
            int n = n0 + nb;
            if (n < NN) {
                int beg = g_off[n], end = g_off[n + 1];
                float d0 = 0.f, d1 = 0.f, s0 = 0.f, s1 = 0.f;
                int e = beg;
                for (; e + 4 <= end; e += 4) {       // 4 independent gathers in flight
                    int a0 = g_srt_src[e];
                    int a1 = g_srt_src[e + 1];
                    int a2 = g_srt_src[e + 2];
                    int a3 = g_srt_src[e + 3];
                    float2 v0 = __half22float2(hhsrc[a0 * 32 + lane]);
                    float2 v1 = __half22float2(hhsrc[a1 * 32 + lane]);
                    float2 v2 = __half22float2(hhsrc[a2 * 32 + lane]);
                    float2 v3 = __half22float2(hhsrc[a3 * 32 + lane]);
                    float m;
                    m = fmaxf(v0.x, 0.f) + MSG_EPS; { float ee = __expf(m); d0 += ee; s0 = fmaf(m, ee, s0); }
                    m = fmaxf(v0.y, 0.f) + MSG_EPS; { float ee = __expf(m); d1 += ee; s1 = fmaf(m, ee, s1); }
                    m = fmaxf(v1.x, 0.f) + MSG_EPS; { float ee = __expf(m); d0 += ee; s0 = fmaf(m, ee, s0); }
                    m = fmaxf(v1.y, 0.f) + MSG_EPS; { float ee = __expf(m); d1 += ee; s1 = fmaf(m, ee, s1); }
                    m = fmaxf(v2.x, 0.f) + MSG_EPS; { float ee = __expf(m); d0 += ee; s0 = fmaf(m, ee, s0); }
                    m = fmaxf(v2.y, 0.f) + MSG_EPS; { float ee = __expf(m); d1 += ee; s1 = fmaf(m, ee, s1); }
                    m = fmaxf(v3.x, 0.f) + MSG_EPS; { float ee = __expf(m); d0 += ee; s0 = fmaf(m, ee, s0); }
                    m = fmaxf(v3.y, 0.f) + MSG_EPS; { float ee = __expf(m); d1 += ee; s1 = fmaf(m, ee, s1); }
                }
                for (; e < end; e++) {
                    int s = g_srt_src[e];
                    float2 v = __half22float2(hhsrc[s * 32 + lane]);
                    float m0 = fmaxf(v.x, 0.f) + MSG_EPS;
                    float m1 = fmaxf(v.y, 0.f) + MSG_EPS;
                    float e0 = __expf(m0);
                    float e1 = __expf(m1);
                    d0 += e0; s0 = fmaf(m0, e0, s0);
                    d1 += e1; s1 = fmaf(m1, e1, s1);
                }
                float2 base2 = *(const float2*)(gsrc + n * HH + lane * 2);  // fp32 self
                float2 o;
                o.x = base2.x + s0 / fmaxf(d0, 1e-16f);   // empty segment -> +0
                o.y = base2.y + s1 / fmaxf(d1, 1e-16f);
                *(float2*)(&ts[nb][lane * 2]) = o;
            }
        }
        __syncthreads();

        // ---- phase B: GEMM (4 nodes/thread) + residual ----
        float acc[4];
        #pragma unroll
        for (int i = 0; i < 4; i++) {
            int n = n0 + nl + 4 * i;
            acc[i] = bj + ((res && n < NN) ? g_h[n * HH + j] : 0.f);
        }
        #pragma unroll
        for (int k = 0; k < HH; k++) {
            float w = Ws[k * HH + j];
            #pragma unroll
            for (int i = 0; i < 4; i++) acc[i] = fmaf(ts[nl + 4 * i][k], w, acc[i]);
        }
        __syncthreads();   // done reading ts before overwrite
        #pragma unroll
        for (int i = 0; i < 4; i++) {
            int n = n0 + nl + 4 * i;
            if (n < NN) g_h[n * HH + j] = acc[i];
            ts[nl + 4 * i][j] = acc[i];
        }

        // ---- phase C: LayerNorm + ReLU -> gdst (fp32) + hhdst (half) ----
        if (write_h2) {
            __syncthreads();
            #pragma unroll
            for (int i = 0; i < 2; i++) {
                int nb = wid * 2 + i;
                int n = n0 + nb;
                if (n >= NN) continue;
                float2 v = *(const float2*)(&ts[nb][lane * 2]);
                float s = v.x + v.y;
                #pragma unroll
                for (int o = 16; o; o >>= 1) s += __shfl_xor_sync(0xffffffffu, s, o);
                float mu = s * (1.f / 64.f);
                float dx = v.x - mu, dy = v.y - mu;
                float vs = dx * dx + dy * dy;
                #pragma unroll
                for (int o = 16; o; o >>= 1) vs += __shfl_xor_sync(0xffffffffu, vs, o);
                float rs = rsqrtf(vs * (1.f / 64.f) + LN_EPS);
                float2 o2;
                o2.x = fmaxf(fmaf(dx * rs, gg.x, bb.x), 0.f);
                o2.y = fmaxf(fmaf(dy * rs, gg.y, bb.y), 0.f);
                *(float2*)(gdst + n * HH + lane * 2) = o2;
                hhdst[n * 32 + lane] = __float22half2_rn(o2);
            }
        }
    }
}

// ---------------- predictor: out = h @ pred_W + pred_b (16 nodes/block, reg-blocked) ----------------
__global__ void __launch_bounds__(224) k_pred(const float* __restrict__ W,
                                              const float* __restrict__ b,
                                              float* __restrict__ out) {
    __shared__ float Ws[HH * OUTF];  // 28 KB
    __shared__ float hs[16][HH];     // 4 KB
    int tid = threadIdx.x;
    int nl = tid / OUTF, j = tid % OUTF;   // nl in 0..1
    int n0 = blockIdx.x * 16;
    for (int i = tid; i < HH * OUTF; i += 224) Ws[i] = W[i];
    for (int i = tid; i < 16 * HH; i += 224) {
        int node = i >> 6, f = i & 63;
        int n = n0 + node;
        hs[node][f] = (n < NN) ? g_h[n * HH + f] : 0.f;
    }
    __syncthreads();
    float bj = b[j];
    float acc[8];
    #pragma unroll
    for (int i = 0; i < 8; i++) acc[i] = bj;
    #pragma unroll
    for (int k = 0; k < HH; k++) {
        float w = Ws[k * OUTF + j];
        #pragma unroll
        for (int i = 0; i < 8; i++) acc[i] = fmaf(hs[nl + 2 * i][k], w, acc[i]);
    }
    #pragma unroll
    for (int i = 0; i < 8; i++) {
        int n = n0 + nl + 2 * i;
        if (n < NN) out[n * OUTF + j] = acc[i];
    }
}

// ---------------- launch ----------------
extern "C" void kernel_launch(void* const* d_in, const int* in_sizes, int n_in,
                              void* d_out, int out_size) {
    const float* x      = (const float*)d_in[0];
    const int*   ei     = (const int*)d_in[1];   // int32 (jax x64 disabled)
    const float* enc_W  = (const float*)d_in[2];
    const float* enc_b  = (const float*)d_in[3];
    const float* ln_g   = (const float*)d_in[4];
    const float* ln_b   = (const float*)d_in[5];
    const float* mlp_W  = (const float*)d_in[6];
    const float* mlp_b  = (const float*)d_in[7];
    const float* pred_W = (const float*)d_in[8];
    const float* pred_b = (const float*)d_in[9];
    float*       out    = (float*)d_out;

    const int* src = ei;
    const int* dst = ei + EE;

    // CSR build (counting sort by dst)
    k_zero<<<(NN + 255) / 256, 256>>>();
    k_hist<<<(EE + 255) / 256, 256>>>(dst);
    k_scan<<<1, 1024>>>();
    k_scatter<<<(EE + 255) / 256, 256>>>(src, dst);

    // encoder (g_h + fp32 bufA + half hhA)
    k_enc<<<(NN + 15) / 16, 256>>>(x, enc_W, enc_b);

    float *bufA = nullptr, *bufB = nullptr;
    __half *hhA = nullptr, *hhB = nullptr;
    cudaGetSymbolAddress((void**)&bufA, g_bufA);
    cudaGetSymbolAddress((void**)&bufB, g_bufB);
    cudaGetSymbolAddress((void**)&hhA, g_hhA);
    cudaGetSymbolAddress((void**)&hhB, g_hhB);

    // layer i: sources = buf/hh[i%2], LN outputs -> buf/hh[(i+1)%2]
    for (int i = 0; i < LL; i++) {
        const float*   gsrc  = (i & 1) ? bufB : bufA;
        float*         gdst  = (i & 1) ? bufA : bufB;
        const __half2* hhsrc = (const __half2*)((i & 1) ? hhB : hhA);
        __half2*       hhdst = (__half2*)((i & 1) ? hhA : hhB);
        k_layer<<<PGRID, 256>>>(mlp_W + i * HH * HH, mlp_b + i * HH,
                                ln_g + i * HH, ln_b + i * HH,
                                gsrc, hhsrc, gdst, hhdst,
                                /*res=*/(i > 0) ? 1 : 0,
                                /*write_h2=*/(i < LL - 1) ? 1 : 0);
    }

    // predictor
    k_pred<<<(NN + 15) / 16, 224>>>(pred_W, pred_b, out);
}